// round 9
// baseline (speedup 1.0000x reference)
#include <cuda_runtime.h>
#include <cstdint>

#define ROWS   81920
#define NCOLS  4096
#define KQ     144              // 3 levels x 48 (45 real + 3 zero pad each)
#define TPC    8                // M-tiles per CTA
#define MSLOTS 80
#define NT     64               // 4096 / 64 N-tiles

__device__ __align__(16) char g_Y [(size_t)ROWS  * KQ];   // 11.8 MB signs (±1 s8, x3 levels)
__device__ __align__(16) char g_Hq[(size_t)NCOLS * KQ];   // 590 KB quantized H
__device__ unsigned long long g_part[(size_t)ROWS * NT];  // winner per (row, ntile)
__device__ int                g_hbits;                    // max|H| as float bits

// ---------------- helpers ----------------
__device__ __forceinline__ uint32_t smem_u32(const void* p) {
    uint32_t a;
    asm("{ .reg .u64 t; cvta.to.shared.u64 t, %1; cvt.u32.u64 %0, t; }" : "=r"(a) : "l"(p));
    return a;
}
__device__ __forceinline__ void cpasync16(uint32_t dst, const void* src) {
    asm volatile("cp.async.cg.shared.global [%0], [%1], 16;" :: "r"(dst), "l"(src) : "memory");
}
#define CP_COMMIT() asm volatile("cp.async.commit_group;" ::: "memory")
#define CP_WAIT0()  asm volatile("cp.async.wait_group 0;" ::: "memory")

#define LDX4(d, addr)                                                              \
    asm volatile("ldmatrix.sync.aligned.m8n8.x4.shared.b16 {%0,%1,%2,%3}, [%4];"   \
        : "=r"((d)[0]), "=r"((d)[1]), "=r"((d)[2]), "=r"((d)[3]) : "r"(addr))

#define IMMA(c, a0, a1, b)                                                         \
    asm volatile("mma.sync.aligned.m16n8k16.row.col.s32.s8.s8.s32 "                \
        "{%0,%1,%2,%3}, {%4,%5}, {%6}, {%0,%1,%2,%3};"                             \
        : "+r"((c)[0]), "+r"((c)[1]), "+r"((c)[2]), "+r"((c)[3])                   \
        : "r"(a0), "r"(a1), "r"(b))

// ---------------------------------------------------------------------------
// K0: zero hmax accumulator
// ---------------------------------------------------------------------------
__global__ void k_zero() { g_hbits = 0; }

// ---------------------------------------------------------------------------
// K0b: hmax = max|H| (positive float bits compare as ints)
// ---------------------------------------------------------------------------
__global__ void k_hmax(const float* __restrict__ H)
{
    int i = blockIdx.x * blockDim.x + threadIdx.x;
    float v = (i < 45 * NCOLS) ? fabsf(H[i]) : 0.f;
    unsigned b = __float_as_uint(v);
    b = __reduce_max_sync(0xffffffffu, b);
    if ((threadIdx.x & 31) == 0) atomicMax(&g_hbits, (int)b);
}

// ---------------------------------------------------------------------------
// K1: sign masks -> s8 rows [±1(45) 0(3)] x3  (bit set -> -1 -> 0xFF)
// ---------------------------------------------------------------------------
__global__ void k_signs(const float* __restrict__ x,
                        const float* __restrict__ S,
                        const float* __restrict__ T)
{
    int i = blockIdx.x * blockDim.x + threadIdx.x;
    if (i >= ROWS) return;
    int token = i / 10, g = i % 10;
    const float* xr = x + (token >> 3) * 480 + (token & 7) * 60;

    unsigned long long mask = 0ull;
#pragma unroll
    for (int cl = 0; cl < 3; cl++) {
        int c = 3 * g + cl;
        float x0 = xr[c * 2 + 0], x1 = xr[c * 2 + 1];
        const float* S0 = S + c * 30;
        const float* S1 = S0 + 15;
        const float* Tc = T + c * 15;
#pragma unroll
        for (int k = 0; k < 15; k++) {
            float y = __fadd_rn(__fmul_rn(x0, S0[k]), __fmul_rn(x1, S1[k]));
            y = __fadd_rn(y, -Tc[k]);
            y = __fadd_rn(y, -1e-4f);
            if (y < 0.f) mask |= 1ull << (cl * 15 + k);
        }
    }

    unsigned blk[12];
#pragma unroll
    for (int w = 0; w < 12; w++) {
        unsigned word = 0;
#pragma unroll
        for (int e = 0; e < 4; e++) {
            int p = 4 * w + e;
            unsigned val = (p < 45) ? (((mask >> p) & 1ull) ? 0xFFu : 0x01u) : 0u;
            word |= val << (8 * e);
        }
        blk[w] = word;
    }
    uint4* yp = reinterpret_cast<uint4*>(g_Y + (size_t)i * KQ);
#pragma unroll
    for (int L = 0; L < 3; L++) {
        yp[L * 3 + 0] = make_uint4(blk[0], blk[1], blk[2],  blk[3]);
        yp[L * 3 + 1] = make_uint4(blk[4], blk[5], blk[6],  blk[7]);
        yp[L * 3 + 2] = make_uint4(blk[8], blk[9], blk[10], blk[11]);
    }
}

// ---------------------------------------------------------------------------
// K2: 3-level int8 quantization of H (global scale from hmax)
// h = s3*(q1*2^14 + q2*2^7 + q3) + r,  |r| <= s3/2,  s3 = hmax/(127*2^15)*2... 
// (s1 = hmax/127, s2 = s1/128, s3 = s2/128; q2,q3 in [-64,64])
// ---------------------------------------------------------------------------
__global__ void k_hconv(const float* __restrict__ H)
{
    int n = blockIdx.x * blockDim.x + threadIdx.x;
    if (n >= NCOLS) return;
    float hmax = __uint_as_float((unsigned)g_hbits);
    float s1 = hmax / 127.f;
    float s2 = s1 * 0.0078125f;       // /128
    float s3 = s2 * 0.0078125f;
    char* row = g_Hq + (size_t)n * KQ;
#pragma unroll 1
    for (int d = 0; d < 45; d++) {
        float h  = H[(size_t)d * NCOLS + n];
        int q1 = __float2int_rn(h / s1);
        float r1 = h - (float)q1 * s1;
        int q2 = __float2int_rn(r1 / s2);
        float r2 = r1 - (float)q2 * s2;
        int q3 = __float2int_rn(r2 / s3);
        row[d] = (char)q1; row[48 + d] = (char)q2; row[96 + d] = (char)q3;
    }
    row[45] = row[46] = row[47] = 0;
    row[93] = row[94] = row[95] = 0;
    row[141] = row[142] = row[143] = 0;
}

// ---------------------------------------------------------------------------
// K3: IMMA GEMM (M128 x N64 x K=3x48) + exact integer argmax epilogue.
// grid 5120: ntile = bid & 63, mslot = bid >> 6 (8 M-tiles each).
// ---------------------------------------------------------------------------
__global__ void __launch_bounds__(256, 1) k_gemm()
{
    __shared__ __align__(16) char sB[64 * KQ];          // 9216
    __shared__ __align__(16) char sA[2][128 * KQ];      // 2 x 18432
    __shared__ unsigned long long win[128][2];          // 2048  (total 48128)

    const int tid = threadIdx.x, wid = tid >> 5, lane = tid & 31;
    const int ntile = blockIdx.x & 63;
    const int mslot = blockIdx.x >> 6;
    const int wm = wid >> 1, wn = wid & 1;              // 4(m) x 2(n) warps

    const uint32_t sBu  = smem_u32(sB);
    const uint32_t sAu0 = smem_u32(sA[0]);
    const uint32_t sAu1 = smem_u32(sA[1]);

    // B tile (64 x 144 s8), layout-preserving linear copy
    {
        const char* hb = g_Hq + (size_t)(ntile * 64) * KQ;
#pragma unroll
        for (int it = 0; it < 3; it++) {
            int c = tid + it * 256;
            if (c < 576) cpasync16(sBu + c * 16, hb + c * 16);
        }
    }
    // A tile 0
    {
        const char* src = g_Y + (size_t)(mslot * TPC) * 128 * KQ;
#pragma unroll
        for (int it = 0; it < 5; it++) {
            int c = tid + it * 256;
            if (c < 1152) cpasync16(sAu0 + c * 16, src + c * 16);
        }
    }
    CP_COMMIT();

    const uint32_t aOff  = (uint32_t)(wm * 32 + lane) * KQ;     // ldmatrix row addr
    const uint32_t bAddr = sBu + (uint32_t)(wn * 32 + lane) * KQ;
    const int lq = lane & 3, lr = lane >> 2;

    for (int i = 0; i < TPC; i++) {
        const int b = i & 1;
        CP_WAIT0();
        __syncthreads();
        if (i < TPC - 1) {                               // prefetch A(i+1)
            const char* src = g_Y + (size_t)((mslot * TPC + i + 1) * 128) * KQ;
            uint32_t dst = b ? sAu0 : sAu1;
#pragma unroll
            for (int it = 0; it < 5; it++) {
                int c = tid + it * 256;
                if (c < 1152) cpasync16(dst + c * 16, src + c * 16);
            }
            CP_COMMIT();
        }

        const uint32_t aBase = (b ? sAu1 : sAu0) + aOff;
        int acc[3][2][4][4];
#pragma unroll
        for (int L = 0; L < 3; L++)
#pragma unroll
            for (int mi = 0; mi < 2; mi++)
#pragma unroll
                for (int t = 0; t < 4; t++)
#pragma unroll
                    for (int e = 0; e < 4; e++) acc[L][mi][t][e] = 0;

#pragma unroll
        for (int L = 0; L < 3; L++) {
#pragma unroll
            for (int s = 0; s < 3; s++) {
                const uint32_t koff = (uint32_t)(L * 48 + s * 16);
                uint32_t a[4], bb[4];
                LDX4(a, aBase + koff);
                LDX4(bb, bAddr + koff);
#pragma unroll
                for (int t = 0; t < 4; t++) {
                    IMMA(acc[L][0][t], a[0], a[1], bb[t]);
                    IMMA(acc[L][1][t], a[2], a[3], bb[t]);
                }
            }
        }

        // Epilogue: exact integer argmax, first-index tie-break
        const int rowbase = (mslot * TPC + i) * 128;
#pragma unroll
        for (int mi = 0; mi < 2; mi++) {
#pragma unroll
            for (int h = 0; h < 2; h++) {
                int bv = 0x80000000; int bc = 0;
#pragma unroll
                for (int t = 0; t < 4; t++) {
                    int v0 = (acc[0][mi][t][2*h]   * 128 + acc[1][mi][t][2*h])   * 128 + acc[2][mi][t][2*h];
                    int v1 = (acc[0][mi][t][2*h+1] * 128 + acc[1][mi][t][2*h+1]) * 128 + acc[2][mi][t][2*h+1];
                    int c0 = wn * 32 + t * 8 + 2 * lq;
                    if (v0 > bv) { bv = v0; bc = c0; }
                    if (v1 > bv) { bv = v1; bc = c0 + 1; }
                }
                unsigned gcol = (unsigned)(ntile * 64 + bc);
                unsigned long long pk =
                    ((unsigned long long)(unsigned)(bv + (1 << 29)) << 32)
                    | (unsigned long long)(4095u - gcol);
#pragma unroll
                for (int off = 1; off < 4; off <<= 1) {
                    unsigned long long o = __shfl_xor_sync(0xffffffffu, pk, off);
                    if (o > pk) pk = o;
                }
                if (lq == 0)
                    win[wm * 32 + mi * 16 + 8 * h + lr][wn] = pk;
            }
        }
        __syncthreads();
        if (tid < 128) {
            unsigned long long v0 = win[tid][0], v1 = win[tid][1];
            if (v1 > v0) v0 = v1;
            g_part[(size_t)(rowbase + tid) * NT + ntile] = v0;
        }
    }
}

// ---------------------------------------------------------------------------
// K4: merge 64 winners per row, LUT gather, write out
// ---------------------------------------------------------------------------
__global__ void k_merge(const float* __restrict__ LUT, float2* __restrict__ out)
{
    int wg   = (blockIdx.x * blockDim.x + threadIdx.x) >> 5;
    int lane = threadIdx.x & 31;
    if (wg >= ROWS) return;

    const unsigned long long* p = g_part + (size_t)wg * NT;
    unsigned long long v = p[lane];
    unsigned long long w = p[lane + 32];
    if (w > v) v = w;

    unsigned hi = (unsigned)(v >> 32);
    unsigned lo = (unsigned)v;
    unsigned mhi  = __reduce_max_sync(0xffffffffu, hi);
    unsigned cand = (hi == mhi) ? lo : 0u;
    unsigned mlo  = __reduce_max_sync(0xffffffffu, cand);

    if (lane == 0) {
        int col = 4095 - (int)mlo;
        int g   = wg % 10;
        const float2* l2 = reinterpret_cast<const float2*>(LUT);
        out[wg] = l2[(size_t)g * NCOLS + col];
    }
}

// ---------------------------------------------------------------------------
extern "C" void kernel_launch(void* const* d_in, const int* in_sizes, int n_in,
                              void* d_out, int out_size)
{
    const float* x   = (const float*)d_in[0];
    const float* S   = (const float*)d_in[1];
    const float* T   = (const float*)d_in[2];
    const float* H   = (const float*)d_in[3];
    const float* LUT = (const float*)d_in[4];
    (void)in_sizes; (void)n_in; (void)out_size;

    k_zero <<<1, 1>>>();
    k_hmax <<<(45 * NCOLS + 255) / 256, 256>>>(H);
    k_hconv<<<NCOLS / 256, 256>>>(H);
    k_signs<<<(ROWS + 255) / 256, 256>>>(x, S, T);
    k_gemm <<<MSLOTS * NT, 256>>>();
    k_merge<<<(ROWS * 32 + 255) / 256, 256>>>(LUT, (float2*)d_out);
}

// round 10
// speedup vs baseline: 4.8345x; 4.8345x over previous
#include <cuda_runtime.h>
#include <cuda_fp16.h>
#include <cstdint>

#define ROWS   81920
#define NCOLS  4096
#define KG     96               // 2 fp16 levels x 48 (45 real + 3 pad)... laid out [y|y|pad6]
#define ROWB   192              // global row bytes (96 fp16)
#define SSTR   208              // smem row stride (13 x 16B -> conflict-free ldmatrix)
#define TPC    8                // M-tiles per CTA
#define MSLOTS 80
#define NT     32               // 4096 / 128 N-tiles

// SMEM: B tile 128x208 = 26624 ; A double buffer 2 x 26624
#define SM_B   0
#define SM_A0  26624
#define SM_A1  53248
#define SM_TOT 79872

__device__ __align__(16) __half        g_Y [(size_t)ROWS  * KG];   // 15.7 MB
__device__ __align__(16) __half        g_Hh[(size_t)NCOLS * KG];   // 786 KB
__device__ unsigned long long          g_part[(size_t)ROWS * NT];  // winner per (row, ntile)

// ---------------- helpers ----------------
__device__ __forceinline__ uint32_t smem_u32(const void* p) {
    uint32_t a;
    asm("{ .reg .u64 t; cvta.to.shared.u64 t, %1; cvt.u32.u64 %0, t; }" : "=r"(a) : "l"(p));
    return a;
}
__device__ __forceinline__ void cpasync16(uint32_t dst, const void* src) {
    asm volatile("cp.async.cg.shared.global [%0], [%1], 16;" :: "r"(dst), "l"(src) : "memory");
}
#define CP_COMMIT() asm volatile("cp.async.commit_group;" ::: "memory")
#define CP_WAIT0()  asm volatile("cp.async.wait_group 0;" ::: "memory")

#define LDX4(d, addr)                                                              \
    asm volatile("ldmatrix.sync.aligned.m8n8.x4.shared.b16 {%0,%1,%2,%3}, [%4];"   \
        : "=r"((d)[0]), "=r"((d)[1]), "=r"((d)[2]), "=r"((d)[3]) : "r"(addr))

#define MMA(c, a, b0, b1)                                                          \
    asm volatile("mma.sync.aligned.m16n8k16.row.col.f32.f16.f16.f32 "              \
        "{%0,%1,%2,%3}, {%4,%5,%6,%7}, {%8,%9}, {%0,%1,%2,%3};"                    \
        : "+f"((c)[0]), "+f"((c)[1]), "+f"((c)[2]), "+f"((c)[3])                   \
        : "r"((a)[0]), "r"((a)[1]), "r"((a)[2]), "r"((a)[3]), "r"(b0), "r"(b1))

// ---------------------------------------------------------------------------
// K1: sign masks -> Y rows (fp16 ±1, K=96 = [y(45)|y(45)|6 zeros])
// ---------------------------------------------------------------------------
__global__ void k_signs(const float* __restrict__ x,
                        const float* __restrict__ S,
                        const float* __restrict__ T)
{
    int i = blockIdx.x * blockDim.x + threadIdx.x;
    if (i >= ROWS) return;
    int token = i / 10, g = i % 10;
    const float* xr = x + (token >> 3) * 480 + (token & 7) * 60;

    unsigned long long mask = 0ull;
#pragma unroll
    for (int cl = 0; cl < 3; cl++) {
        int c = 3 * g + cl;
        float x0 = xr[c * 2 + 0], x1 = xr[c * 2 + 1];
        const float* S0 = S + c * 30;
        const float* S1 = S0 + 15;
        const float* Tc = T + c * 15;
#pragma unroll
        for (int k = 0; k < 15; k++) {
            float y = __fadd_rn(__fmul_rn(x0, S0[k]), __fmul_rn(x1, S1[k]));
            y = __fadd_rn(y, -Tc[k]);
            y = __fadd_rn(y, -1e-4f);
            if (y < 0.f) mask |= 1ull << (cl * 15 + k);
        }
    }

    uint4* yp = reinterpret_cast<uint4*>(g_Y + (size_t)i * KG);
#pragma unroll
    for (int q = 0; q < 12; q++) {
        unsigned w[4];
#pragma unroll
        for (int e = 0; e < 4; e++) {
            int p0 = q * 8 + e * 2, p1 = p0 + 1;
            unsigned lo = 0, hi = 0;
            if (p0 < 90) lo = 0x3C00u | ((unsigned)((mask >> (p0 % 45)) & 1ull) << 15);
            if (p1 < 90) hi = 0x3C00u | ((unsigned)((mask >> (p1 % 45)) & 1ull) << 15);
            w[e] = lo | (hi << 16);
        }
        yp[q] = make_uint4(w[0], w[1], w[2], w[3]);
    }
}

// ---------------------------------------------------------------------------
// K2: exact 2-way fp16 split of H -> g_Hh[n][k], k = j*45 + d, pad zeroed
// ---------------------------------------------------------------------------
__global__ void k_hconv(const float* __restrict__ H)
{
    int n = blockIdx.x * blockDim.x + threadIdx.x;
    if (n >= NCOLS) return;
    __half* row = g_Hh + (size_t)n * KG;
    for (int d = 0; d < 45; d++) {
        float h = H[(size_t)d * NCOLS + n];
        __half f1 = __float2half_rn(h);
        float r1 = h - __half2float(f1);
        row[d] = f1; row[45 + d] = __float2half_rn(r1);
    }
    for (int p = 90; p < KG; p++) row[p] = __float2half_rn(0.f);
}

// ---------------------------------------------------------------------------
// K3: fp16 mma.sync GEMM + register argmax epilogue.
// grid 2560: ntile = bid & 31 (128 cols), mslot = bid >> 5 (8 M-tiles of 128).
// ---------------------------------------------------------------------------
__device__ __forceinline__ void load_A(uint32_t dst, int grow0, int tid)
{
    const char* src = (const char*)g_Y + (size_t)grow0 * ROWB;
#pragma unroll
    for (int it = 0; it < 6; it++) {
        int c = tid + it * 256;                  // 1536 chunks: 128 rows x 12
        int r = c / 12, kc = c - r * 12;
        cpasync16(dst + (uint32_t)(r * SSTR + kc * 16), src + (size_t)r * ROWB + kc * 16);
    }
}

__global__ void __launch_bounds__(256, 1) k_gemm()
{
    extern __shared__ char smem[];
    __shared__ unsigned long long win[128][2];
    uint32_t sb = smem_u32(smem);
    const int tid = threadIdx.x, wid = tid >> 5, lane = tid & 31;
    const int ntile = blockIdx.x & 31;
    const int mslot = blockIdx.x >> 5;
    const int wm = wid >> 1, wn = wid & 1;       // warp grid 4(m) x 2(n)

    // B tile: 128 n-rows x 96 k (resident)
    {
        const char* hb = (const char*)g_Hh + (size_t)(ntile * 128) * ROWB;
#pragma unroll
        for (int it = 0; it < 6; it++) {
            int c = tid + it * 256;
            int r = c / 12, kc = c - r * 12;
            cpasync16(sb + SM_B + (uint32_t)(r * SSTR + kc * 16), hb + (size_t)r * ROWB + kc * 16);
        }
    }
    load_A(sb + SM_A0, mslot * TPC * 128, tid);
    CP_COMMIT();

    // ldmatrix lane offsets
    const int j = lane >> 3, lr = lane & 7;
    const uint32_t aoff = (uint32_t)((wm * 32 + (j & 1) * 8 + lr) * SSTR + (j >> 1) * 16);
    const uint32_t boff = sb + SM_B + (uint32_t)((wn * 64 + (j >> 1) * 8 + lr) * SSTR + (j & 1) * 16);
    const int lq = lane & 3;                     // column sub-lane
    const int lrow = lane >> 2;                  // row within m16

    for (int i = 0; i < TPC; i++) {
        const int b = i & 1;
        CP_WAIT0();                              // A(i) (and B at i=0) resident
        __syncthreads();
        if (i < TPC - 1) {                       // prefetch A(i+1) into other buffer
            load_A(sb + (b ? SM_A0 : SM_A1), (mslot * TPC + i + 1) * 128, tid);
            CP_COMMIT();
        }

        const uint32_t abase = sb + (b ? SM_A1 : SM_A0) + aoff;
        float acc[2][8][4];
#pragma unroll
        for (int mb = 0; mb < 2; mb++)
#pragma unroll
            for (int nb = 0; nb < 8; nb++)
#pragma unroll
                for (int e = 0; e < 4; e++) acc[mb][nb][e] = 0.f;

#pragma unroll
        for (int ks = 0; ks < 6; ks++) {
            uint32_t a0[4], a1[4], bb[4][4];
            LDX4(a0, abase + ks * 32);
            LDX4(a1, abase + ks * 32 + 16 * SSTR);
#pragma unroll
            for (int n16 = 0; n16 < 4; n16++)
                LDX4(bb[n16], boff + (uint32_t)(n16 * 16 * SSTR) + ks * 32);
#pragma unroll
            for (int nb = 0; nb < 8; nb++) {
                const uint32_t* bp = bb[nb >> 1];
                uint32_t blo = (nb & 1) ? bp[2] : bp[0];
                uint32_t bhi = (nb & 1) ? bp[3] : bp[1];
                MMA(acc[0][nb], a0, blo, bhi);
                MMA(acc[1][nb], a1, blo, bhi);
            }
        }

        // Epilogue: per (mb, h) row argmax over this warp's 64 columns
        const int rowbase = (mslot * TPC + i) * 128;
        const int colbase = ntile * 128 + wn * 64 + 2 * lq;
#pragma unroll
        for (int mb = 0; mb < 2; mb++) {
#pragma unroll
            for (int h = 0; h < 2; h++) {
                float bv = -__int_as_float(0x7f800000);   // -inf
                int   bc = 0;
#pragma unroll
                for (int nb = 0; nb < 8; nb++) {
                    float v0 = acc[mb][nb][2 * h];
                    float v1 = acc[mb][nb][2 * h + 1];
                    int c0 = colbase + nb * 8;
                    if (v0 > bv) { bv = v0; bc = c0; }       // strict >: first index
                    if (v1 > bv) { bv = v1; bc = c0 + 1; }
                }
                unsigned u   = __float_as_uint(bv);
                unsigned key = u ^ (unsigned)(((int)u >> 31) | 0x80000000);
                unsigned long long pk =
                    ((unsigned long long)key << 32) | (unsigned long long)(4095u - (unsigned)bc);
#pragma unroll
                for (int off = 1; off < 4; off <<= 1) {
                    unsigned long long o = __shfl_xor_sync(0xffffffffu, pk, off);
                    if (o > pk) pk = o;
                }
                if (lq == 0)
                    win[wm * 32 + mb * 16 + h * 8 + lrow][wn] = pk;
            }
        }
        __syncthreads();
        if (tid < 128) {
            unsigned long long v0 = win[tid][0], v1 = win[tid][1];
            if (v1 > v0) v0 = v1;
            g_part[(size_t)(rowbase + tid) * NT + ntile] = v0;
        }
    }
}

// ---------------------------------------------------------------------------
// K4: merge 32 winners per row, LUT gather, write out
// ---------------------------------------------------------------------------
__global__ void k_merge(const float* __restrict__ LUT, float2* __restrict__ out)
{
    int wg   = (blockIdx.x * blockDim.x + threadIdx.x) >> 5;
    int lane = threadIdx.x & 31;
    if (wg >= ROWS) return;

    unsigned long long v = g_part[(size_t)wg * NT + lane];
    unsigned hi = (unsigned)(v >> 32);
    unsigned lo = (unsigned)v;
    unsigned mhi  = __reduce_max_sync(0xffffffffu, hi);
    unsigned cand = (hi == mhi) ? lo : 0u;
    unsigned mlo  = __reduce_max_sync(0xffffffffu, cand);

    if (lane == 0) {
        int col = 4095 - (int)mlo;
        int g   = wg % 10;
        const float2* l2 = reinterpret_cast<const float2*>(LUT);
        out[wg] = l2[(size_t)g * NCOLS + col];
    }
}

// ---------------------------------------------------------------------------
extern "C" void kernel_launch(void* const* d_in, const int* in_sizes, int n_in,
                              void* d_out, int out_size)
{
    const float* x   = (const float*)d_in[0];
    const float* S   = (const float*)d_in[1];
    const float* T   = (const float*)d_in[2];
    const float* H   = (const float*)d_in[3];
    const float* LUT = (const float*)d_in[4];
    (void)in_sizes; (void)n_in; (void)out_size;

    cudaFuncSetAttribute(k_gemm, cudaFuncAttributeMaxDynamicSharedMemorySize, SM_TOT);

    k_signs<<<(ROWS + 255) / 256, 256>>>(x, S, T);
    k_hconv<<<NCOLS / 256, 256>>>(H);
    k_gemm<<<MSLOTS * NT, 256, SM_TOT>>>();
    k_merge<<<(ROWS * 32 + 255) / 256, 256>>>(LUT, (float2*)d_out);
}

// round 11
// speedup vs baseline: 6.2649x; 1.2959x over previous
#include <cuda_runtime.h>
#include <cuda_fp16.h>
#include <cstdint>

#define ROWS   81920
#define NCOLS  4096
#define KG     96               // 2 fp16 levels x 48 (45 real + 3 pad), [y|y|pad6]
#define ROWB   192              // global row bytes (96 fp16)
#define SSTR   208              // smem row stride (13 x 16B -> conflict-free ldmatrix)
#define TPC    8                // M-tiles per CTA
#define MSLOTS 80
#define NT     32               // 4096 / 128 N-tiles

// SMEM: B tile 128x208 = 26624 ; A double buffer 2 x 26624
#define SM_B   0
#define SM_A0  26624
#define SM_A1  53248
#define SM_TOT 79872

__device__ __align__(16) __half        g_Y [(size_t)ROWS  * KG];   // 15.7 MB
__device__ __align__(16) __half        g_Hh[(size_t)NCOLS * KG];   // 786 KB
__device__ unsigned long long          g_best[ROWS];               // packed (key | 4095-col)

// ---------------- helpers ----------------
__device__ __forceinline__ uint32_t smem_u32(const void* p) {
    uint32_t a;
    asm("{ .reg .u64 t; cvta.to.shared.u64 t, %1; cvt.u32.u64 %0, t; }" : "=r"(a) : "l"(p));
    return a;
}
__device__ __forceinline__ void cpasync16(uint32_t dst, const void* src) {
    asm volatile("cp.async.cg.shared.global [%0], [%1], 16;" :: "r"(dst), "l"(src) : "memory");
}
#define CP_COMMIT() asm volatile("cp.async.commit_group;" ::: "memory")
#define CP_WAIT0()  asm volatile("cp.async.wait_group 0;" ::: "memory")

#define LDX4(d, addr)                                                              \
    asm volatile("ldmatrix.sync.aligned.m8n8.x4.shared.b16 {%0,%1,%2,%3}, [%4];"   \
        : "=r"((d)[0]), "=r"((d)[1]), "=r"((d)[2]), "=r"((d)[3]) : "r"(addr))

#define MMA(c, a, b0, b1)                                                          \
    asm volatile("mma.sync.aligned.m16n8k16.row.col.f32.f16.f16.f32 "              \
        "{%0,%1,%2,%3}, {%4,%5,%6,%7}, {%8,%9}, {%0,%1,%2,%3};"                    \
        : "+f"((c)[0]), "+f"((c)[1]), "+f"((c)[2]), "+f"((c)[3])                   \
        : "r"((a)[0]), "r"((a)[1]), "r"((a)[2]), "r"((a)[3]), "r"(b0), "r"(b1))

// ---------------------------------------------------------------------------
// K1: sign masks -> Y rows (fp16 ±1, K=96 = [y(45)|y(45)|6 zeros])
// ---------------------------------------------------------------------------
__global__ void k_signs(const float* __restrict__ x,
                        const float* __restrict__ S,
                        const float* __restrict__ T)
{
    int i = blockIdx.x * blockDim.x + threadIdx.x;
    if (i >= ROWS) return;
    int token = i / 10, g = i % 10;
    const float* xr = x + (token >> 3) * 480 + (token & 7) * 60;

    unsigned long long mask = 0ull;
#pragma unroll
    for (int cl = 0; cl < 3; cl++) {
        int c = 3 * g + cl;
        float x0 = xr[c * 2 + 0], x1 = xr[c * 2 + 1];
        const float* S0 = S + c * 30;
        const float* S1 = S0 + 15;
        const float* Tc = T + c * 15;
#pragma unroll
        for (int k = 0; k < 15; k++) {
            float y = __fadd_rn(__fmul_rn(x0, S0[k]), __fmul_rn(x1, S1[k]));
            y = __fadd_rn(y, -Tc[k]);
            y = __fadd_rn(y, -1e-4f);
            if (y < 0.f) mask |= 1ull << (cl * 15 + k);
        }
    }

    uint4* yp = reinterpret_cast<uint4*>(g_Y + (size_t)i * KG);
#pragma unroll
    for (int q = 0; q < 12; q++) {
        unsigned w[4];
#pragma unroll
        for (int e = 0; e < 4; e++) {
            int p0 = q * 8 + e * 2, p1 = p0 + 1;
            unsigned lo = 0, hi = 0;
            if (p0 < 90) lo = 0x3C00u | ((unsigned)((mask >> (p0 % 45)) & 1ull) << 15);
            if (p1 < 90) hi = 0x3C00u | ((unsigned)((mask >> (p1 % 45)) & 1ull) << 15);
            w[e] = lo | (hi << 16);
        }
        yp[q] = make_uint4(w[0], w[1], w[2], w[3]);
    }
}

// ---------------------------------------------------------------------------
// K2: exact 2-way fp16 split of H -> g_Hh[n][k], k = j*45 + d, pad zeroed
// ---------------------------------------------------------------------------
__global__ void k_hconv(const float* __restrict__ H)
{
    int n = blockIdx.x * blockDim.x + threadIdx.x;
    if (n >= NCOLS) return;
    __half* row = g_Hh + (size_t)n * KG;
    for (int d = 0; d < 45; d++) {
        float h = H[(size_t)d * NCOLS + n];
        __half f1 = __float2half_rn(h);
        float r1 = h - __half2float(f1);
        row[d] = f1; row[45 + d] = __float2half_rn(r1);
    }
    for (int p = 90; p < KG; p++) row[p] = __float2half_rn(0.f);
}

// ---------------------------------------------------------------------------
// K3: fp16 mma.sync GEMM + RED.MAX.U64 argmax epilogue.
// grid 2560: ntile = bid & 31 (128 cols), mslot = bid >> 5 (8 M-tiles of 128).
// 2 CTAs/SM so one CTA's MMAs hide the other's epilogue + DMA waits.
// ---------------------------------------------------------------------------
__device__ __forceinline__ void load_A(uint32_t dst, int grow0, int tid)
{
    const char* src = (const char*)g_Y + (size_t)grow0 * ROWB;
#pragma unroll
    for (int it = 0; it < 6; it++) {
        int c = tid + it * 256;                  // 1536 chunks: 128 rows x 12
        int r = c / 12, kc = c - r * 12;
        cpasync16(dst + (uint32_t)(r * SSTR + kc * 16), src + (size_t)r * ROWB + kc * 16);
    }
}

__global__ void __launch_bounds__(256, 2) k_gemm()
{
    extern __shared__ char smem[];
    uint32_t sb = smem_u32(smem);
    const int tid = threadIdx.x, wid = tid >> 5, lane = tid & 31;
    const int ntile = blockIdx.x & 31;
    const int mslot = blockIdx.x >> 5;
    const int wm = wid >> 1, wn = wid & 1;       // warp grid 4(m) x 2(n)

    // B tile: 128 n-rows x 96 k (resident)
    {
        const char* hb = (const char*)g_Hh + (size_t)(ntile * 128) * ROWB;
#pragma unroll
        for (int it = 0; it < 6; it++) {
            int c = tid + it * 256;
            int r = c / 12, kc = c - r * 12;
            cpasync16(sb + SM_B + (uint32_t)(r * SSTR + kc * 16), hb + (size_t)r * ROWB + kc * 16);
        }
    }
    load_A(sb + SM_A0, mslot * TPC * 128, tid);
    CP_COMMIT();

    // ldmatrix lane offsets
    const int j = lane >> 3, lr = lane & 7;
    const uint32_t aoff = (uint32_t)((wm * 32 + (j & 1) * 8 + lr) * SSTR + (j >> 1) * 16);
    const uint32_t boff = sb + SM_B + (uint32_t)((wn * 64 + (j >> 1) * 8 + lr) * SSTR + (j & 1) * 16);
    const int lq = lane & 3;                     // column sub-lane
    const int lrow = lane >> 2;                  // row within m16

    for (int i = 0; i < TPC; i++) {
        const int b = i & 1;
        CP_WAIT0();                              // A(i) (and B at i=0) resident
        __syncthreads();                         // all warps past reads of the other buffer
        if (i < TPC - 1) {                       // prefetch A(i+1) into other buffer
            load_A(sb + (b ? SM_A0 : SM_A1), (mslot * TPC + i + 1) * 128, tid);
            CP_COMMIT();
        }

        const uint32_t abase = sb + (b ? SM_A1 : SM_A0) + aoff;
        float acc[2][8][4];
#pragma unroll
        for (int mb = 0; mb < 2; mb++)
#pragma unroll
            for (int nb = 0; nb < 8; nb++)
#pragma unroll
                for (int e = 0; e < 4; e++) acc[mb][nb][e] = 0.f;

#pragma unroll
        for (int ks = 0; ks < 6; ks++) {
            uint32_t a0[4], a1[4];
            LDX4(a0, abase + ks * 32);
            LDX4(a1, abase + ks * 32 + 16 * SSTR);
#pragma unroll
            for (int n16 = 0; n16 < 4; n16++) {  // consume B frags immediately (reg pressure)
                uint32_t bb[4];
                LDX4(bb, boff + (uint32_t)(n16 * 16 * SSTR) + ks * 32);
                MMA(acc[0][2 * n16],     a0, bb[0], bb[1]);
                MMA(acc[1][2 * n16],     a1, bb[0], bb[1]);
                MMA(acc[0][2 * n16 + 1], a0, bb[2], bb[3]);
                MMA(acc[1][2 * n16 + 1], a1, bb[2], bb[3]);
            }
        }

        // Epilogue: per (mb, h) row argmax over this warp's 64 columns -> RED.MAX
        const int rowbase = (mslot * TPC + i) * 128 + wm * 32 + lrow;
        const int colbase = ntile * 128 + wn * 64 + 2 * lq;
#pragma unroll
        for (int mb = 0; mb < 2; mb++) {
#pragma unroll
            for (int h = 0; h < 2; h++) {
                float bv = -__int_as_float(0x7f800000);   // -inf
                int   bc = 0;
#pragma unroll
                for (int nb = 0; nb < 8; nb++) {
                    float v0 = acc[mb][nb][2 * h];
                    float v1 = acc[mb][nb][2 * h + 1];
                    int c0 = colbase + nb * 8;
                    if (v0 > bv) { bv = v0; bc = c0; }       // strict >: first index
                    if (v1 > bv) { bv = v1; bc = c0 + 1; }
                }
                unsigned u   = __float_as_uint(bv);
                unsigned key = u ^ (unsigned)(((int)u >> 31) | 0x80000000);
                unsigned long long pk =
                    ((unsigned long long)key << 32) | (unsigned long long)(4095u - (unsigned)bc);
#pragma unroll
                for (int off = 1; off < 4; off <<= 1) {
                    unsigned long long o = __shfl_xor_sync(0xffffffffu, pk, off);
                    if (o > pk) pk = o;
                }
                if (lq == 0)
                    atomicMax(&g_best[rowbase + mb * 16 + h * 8], pk);
            }
        }
    }
}

// ---------------------------------------------------------------------------
// K4: per-row LUT gather from the global winner word
// ---------------------------------------------------------------------------
__global__ void k_merge(const float* __restrict__ LUT, float2* __restrict__ out)
{
    int wg = blockIdx.x * blockDim.x + threadIdx.x;
    if (wg >= ROWS) return;
    unsigned long long v = g_best[wg];
    int col = 4095 - (int)(unsigned)v;
    int g   = wg % 10;
    const float2* l2 = reinterpret_cast<const float2*>(LUT);
    out[wg] = l2[(size_t)g * NCOLS + col];
}

// ---------------------------------------------------------------------------
extern "C" void kernel_launch(void* const* d_in, const int* in_sizes, int n_in,
                              void* d_out, int out_size)
{
    const float* x   = (const float*)d_in[0];
    const float* S   = (const float*)d_in[1];
    const float* T   = (const float*)d_in[2];
    const float* H   = (const float*)d_in[3];
    const float* LUT = (const float*)d_in[4];
    (void)in_sizes; (void)n_in; (void)out_size;

    cudaFuncSetAttribute(k_gemm, cudaFuncAttributeMaxDynamicSharedMemorySize, SM_TOT);

    k_signs<<<(ROWS + 255) / 256, 256>>>(x, S, T);
    k_hconv<<<NCOLS / 256, 256>>>(H);
    k_gemm<<<MSLOTS * NT, 256, SM_TOT>>>();
    k_merge<<<(ROWS + 255) / 256, 256>>>(LUT, (float2*)d_out);
}